// round 15
// baseline (speedup 1.0000x reference)
#include <cuda_runtime.h>
#include <cuda_bf16.h>
#include <cstdint>

// ---------------- problem constants ----------------
namespace cfg {
constexpr int N = 100000;
constexpr int E = 1600000;
constexpr int G = 64;
constexpr int LAYERS = 4;
constexpr float EPS = 1e-6f;
constexpr int NT = (N + 127) / 128;   // 782 row tiles

constexpr size_t aln(size_t x){ return (x + 255) & ~size_t(255); }
constexpr size_t OFF_DEG   = 0;
constexpr size_t OFF_CUR   = OFF_DEG   + aln(sizeof(int)*N);
constexpr size_t OFF_OFFS  = OFF_CUR   + aln(sizeof(int)*(size_t)N);
constexpr size_t OFF_BSUM  = OFF_OFFS  + aln(sizeof(int)*(size_t)(N+1));
constexpr size_t OFF_CSR   = OFF_BSUM  + aln(sizeof(int)*256);
constexpr size_t OFF_GST   = OFF_CSR   + aln(sizeof(int)*(size_t)E);
constexpr size_t OFF_BASES = OFF_GST   + aln(sizeof(int)*(G+1));
constexpr size_t OFF_W     = OFF_BASES + aln(sizeof(float)*(size_t)N*64);
constexpr size_t OFF_GC    = OFF_W     + aln(sizeof(float)*(size_t)N*96);
constexpr size_t OFF_GS    = OFF_GC    + aln(sizeof(float)*(size_t)N*128);
constexpr size_t OFF_GV    = OFF_GS    + aln(sizeof(float)*(size_t)G*128);
constexpr size_t TOTAL     = OFF_GV    + aln(sizeof(float)*(size_t)G*128);
}

__device__ __align__(256) unsigned char g_scratch[cfg::TOTAL];

// ---------------- mma helpers ----------------
__device__ __forceinline__ uint32_t bf2_u32(__nv_bfloat162 v){
    return *reinterpret_cast<uint32_t*>(&v);
}
__device__ __forceinline__ void mma_bf16(float* c, const uint32_t* a, uint32_t b0, uint32_t b1){
    asm volatile(
        "mma.sync.aligned.m16n8k16.row.col.f32.bf16.bf16.f32 "
        "{%0,%1,%2,%3}, {%4,%5,%6,%7}, {%8,%9}, {%0,%1,%2,%3};"
        : "+f"(c[0]), "+f"(c[1]), "+f"(c[2]), "+f"(c[3])
        : "r"(a[0]), "r"(a[1]), "r"(a[2]), "r"(a[3]), "r"(b0), "r"(b1));
}
__device__ __forceinline__ void split_bf16(float2 v, uint32_t& hi, uint32_t& lo){
    __nv_bfloat162 h2 = __floats2bfloat162_rn(v.x, v.y);
    __nv_bfloat162 l2 = __floats2bfloat162_rn(v.x - __low2float(h2),
                                              v.y - __high2float(h2));
    hi = bf2_u32(h2); lo = bf2_u32(l2);
}

// ---------------- small utility kernels ----------------
__global__ void k_zero(unsigned int* __restrict__ p, int n){
    int i = blockIdx.x * blockDim.x + threadIdx.x;
    if (i < n) p[i] = 0u;
}
__global__ void k_hist(const int* __restrict__ ei, int* __restrict__ deg){
    int e = blockIdx.x * blockDim.x + threadIdx.x;
    if (e < cfg::E) atomicAdd(&deg[ei[cfg::E + e]], 1);
}
__global__ void k_scan1(const int* __restrict__ deg, int* __restrict__ offs,
                        int* __restrict__ bsum){
    __shared__ int sm[1024];
    int tid = threadIdx.x;
    int i = blockIdx.x * 1024 + tid;
    int v = (i < cfg::N) ? deg[i] : 0;
    sm[tid] = v; __syncthreads();
    for (int d = 1; d < 1024; d <<= 1){
        int t = (tid >= d) ? sm[tid - d] : 0;
        __syncthreads(); sm[tid] += t; __syncthreads();
    }
    if (i < cfg::N) offs[i + 1] = sm[tid];
    if (tid == 1023) bsum[blockIdx.x] = sm[1023];
}
__global__ void k_scan2(int* __restrict__ bsum, int nb){
    __shared__ int sm[128];
    int tid = threadIdx.x;
    int v = (tid < nb) ? bsum[tid] : 0;
    sm[tid] = v; __syncthreads();
    for (int d = 1; d < 128; d <<= 1){
        int t = (tid >= d) ? sm[tid - d] : 0;
        __syncthreads(); sm[tid] += t; __syncthreads();
    }
    if (tid < nb) bsum[tid] = sm[tid] - v;
}
__global__ void k_scan3(int* __restrict__ offs, const int* __restrict__ bsum){
    int i = blockIdx.x * blockDim.x + threadIdx.x;
    if (i < cfg::N) offs[i + 1] += bsum[i >> 10];
    if (i == 0) offs[0] = 0;
}
__global__ void k_fill(const int* __restrict__ ei, const int* __restrict__ offs,
                       int* __restrict__ cur, int* __restrict__ csr){
    int e = blockIdx.x * blockDim.x + threadIdx.x;
    if (e < cfg::E){
        int d = ei[cfg::E + e];
        int pos = offs[d] + atomicAdd(&cur[d], 1);
        csr[pos] = ei[e];
    }
}
__global__ void k_gstart(const int* __restrict__ npg, int* __restrict__ gs){
    if (blockIdx.x == 0 && threadIdx.x == 0){
        int run = 0;
        for (int g = 0; g < cfg::G; g++){ gs[g] = run; run += npg[g]; }
        gs[cfg::G] = run;
    }
}

// ------ bf16 3-pass GEMM via mma.sync m16n8k16: [M,128] @ [128,NOUT] ------
// R5/R9 configuration (best measured): full NOUT per CTA, A fragments from
// global with 2-deep prefetch, B in smem as separate hi/lo arrays. 2 CTAs/SM.
template<int NOUT, int S0>
__global__ void __launch_bounds__(256, 2)
k_mma(const float* __restrict__ A, int M,
      const float* __restrict__ W0, const float* __restrict__ W1,
      const float* __restrict__ bias0, const float* __restrict__ bias1,
      float* __restrict__ out0, float* __restrict__ out1){
    constexpr int S1  = NOUT - S0;
    constexpr int NT8 = NOUT / 8;
    extern __shared__ uint32_t smu[];
    uint32_t* Bhi = smu;                      // [NOUT][64] packed bf16x2
    uint32_t* Blo = Bhi + NOUT * 64;

    int tid = threadIdx.x;
    int w = tid >> 5, lane = tid & 31;
    int row0 = blockIdx.x * 128;

    // ---- stage B hi/lo: Bcol[n][p], swizzle p ^= (n&7)<<2 ----
    #pragma unroll 2
    for (int idx = tid; idx < 64 * S0; idx += 256){
        int p = idx / S0, n = idx - p * S0;
        float f0 = W0[(size_t)(2 * p) * S0 + n];
        float f1 = W0[(size_t)(2 * p + 1) * S0 + n];
        uint32_t hi, lo;
        split_bf16(make_float2(f0, f1), hi, lo);
        int pos = n * 64 + (p ^ ((n & 7) << 2));
        Bhi[pos] = hi; Blo[pos] = lo;
    }
    if constexpr (S1 > 0){
        #pragma unroll 2
        for (int idx = tid; idx < 64 * S1; idx += 256){
            int p = idx / S1, n = idx - p * S1;
            float f0 = W1[(size_t)(2 * p) * S1 + n];
            float f1 = W1[(size_t)(2 * p + 1) * S1 + n];
            uint32_t hi, lo;
            split_bf16(make_float2(f0, f1), hi, lo);
            int nn = S0 + n;
            int pos = nn * 64 + (p ^ ((nn & 7) << 2));
            Bhi[pos] = hi; Blo[pos] = lo;
        }
    }
    __syncthreads();

    float acc[NT8][4];
    #pragma unroll
    for (int t = 0; t < NT8; t++)
        #pragma unroll
        for (int j = 0; j < 4; j++) acc[t][j] = 0.f;

    int l4 = lane & 3, g = lane >> 2;
    int r1 = w * 16 + g;
    int gr1 = row0 + r1, gr2 = gr1 + 8;
    int cr1 = min(gr1, M - 1), cr2 = min(gr2, M - 1);
    const float2* pA1 = reinterpret_cast<const float2*>(A) + (size_t)cr1 * 64 + l4;
    const float2* pA2 = reinterpret_cast<const float2*>(A) + (size_t)cr2 * 64 + l4;

    // 2-deep ping-pong prefetch of A fragments
    float2 xb[2][4];
    #pragma unroll
    for (int j = 0; j < 2; j++){
        xb[j][0] = pA1[j * 8];     xb[j][1] = pA2[j * 8];
        xb[j][2] = pA1[j * 8 + 4]; xb[j][3] = pA2[j * 8 + 4];
    }
    int swz = g << 2;

    #pragma unroll
    for (int k0 = 0; k0 < 8; k0++){            // k-pair base = k0*8 (16 floats)
        uint32_t ah[4], al[4];
        split_bf16(xb[k0 & 1][0], ah[0], al[0]);
        split_bf16(xb[k0 & 1][1], ah[1], al[1]);
        split_bf16(xb[k0 & 1][2], ah[2], al[2]);
        split_bf16(xb[k0 & 1][3], ah[3], al[3]);
        if (k0 < 6){
            xb[k0 & 1][0] = pA1[(k0 + 2) * 8];     xb[k0 & 1][1] = pA2[(k0 + 2) * 8];
            xb[k0 & 1][2] = pA1[(k0 + 2) * 8 + 4]; xb[k0 & 1][3] = pA2[(k0 + 2) * 8 + 4];
        }
        int c0 = (k0 * 8 + l4) ^ swz;
        int c1 = (k0 * 8 + 4 + l4) ^ swz;
        #pragma unroll
        for (int nt = 0; nt < NT8; nt++){
            int nb = (nt * 8 + g) * 64;
            uint32_t bh0 = Bhi[nb + c0], bh1 = Bhi[nb + c1];
            uint32_t bl0 = Blo[nb + c0], bl1 = Blo[nb + c1];
            mma_bf16(acc[nt], ah, bh0, bh1);
            mma_bf16(acc[nt], ah, bl0, bl1);
            mma_bf16(acc[nt], al, bh0, bh1);
        }
    }

    // ---- epilogue ----
    #pragma unroll
    for (int nt = 0; nt < NT8; nt++){
        int col = nt * 8 + 2 * l4;
        float b0 = 0.f, b1 = 0.f;
        float* o;
        int width, oc;
        if (nt * 8 < S0){
            o = out0; width = S0; oc = col;
            if (bias0){ b0 = bias0[oc]; b1 = bias0[oc + 1]; }
        } else {
            o = out1; width = S1; oc = col - S0;
            if (bias1){ b0 = bias1[oc]; b1 = bias1[oc + 1]; }
        }
        if (gr1 < M)
            *reinterpret_cast<float2*>(&o[(size_t)gr1 * width + oc]) =
                make_float2(acc[nt][0] + b0, acc[nt][1] + b1);
        if (gr2 < M)
            *reinterpret_cast<float2*>(&o[(size_t)gr2 * width + oc]) =
                make_float2(acc[nt][2] + b0, acc[nt][3] + b1);
    }
}

// ---- fused aggregate (sum/mean/max over CSR) + combine ----
// One warp per node; shfl index distribution; 8-wide MLP in the gather loop
// (ONLY change vs the measured-best R9 version).
__global__ void __launch_bounds__(256) k_agg(
        const float* __restrict__ bases, const float* __restrict__ wmat,
        const int* __restrict__ offs, const int* __restrict__ csr,
        const float* __restrict__ convb, float* __restrict__ gconv){
    __shared__ float  wsm[8][96];
    __shared__ float2 part2[8][4][66];
    int tid = threadIdx.x;
    int ni = tid >> 5;
    int lane = tid & 31;
    int node = blockIdx.x * 8 + ni;

    for (int i = lane; i < 96; i += 32) wsm[ni][i] = wmat[(size_t)node * 96 + i];

    int beg = offs[node], end = offs[node + 1];
    const float2* bases2 = reinterpret_cast<const float2*>(bases);
    float ninf = __int_as_float(0xff800000);
    float2 s  = make_float2(0.f, 0.f);
    float2 mx = make_float2(ninf, ninf);

    for (int j0 = beg; j0 < end; j0 += 32){
        int myv = (j0 + lane < end) ? csr[j0 + lane] : 0;
        int cnt = min(32, end - j0);
        int jj = 0;
        for (; jj + 8 <= cnt; jj += 8){
            int i0 = __shfl_sync(0xffffffffu, myv, jj);
            int i1 = __shfl_sync(0xffffffffu, myv, jj + 1);
            int i2 = __shfl_sync(0xffffffffu, myv, jj + 2);
            int i3 = __shfl_sync(0xffffffffu, myv, jj + 3);
            int i4 = __shfl_sync(0xffffffffu, myv, jj + 4);
            int i5 = __shfl_sync(0xffffffffu, myv, jj + 5);
            int i6 = __shfl_sync(0xffffffffu, myv, jj + 6);
            int i7 = __shfl_sync(0xffffffffu, myv, jj + 7);
            float2 v0 = bases2[(size_t)i0 * 32 + lane];
            float2 v1 = bases2[(size_t)i1 * 32 + lane];
            float2 v2 = bases2[(size_t)i2 * 32 + lane];
            float2 v3 = bases2[(size_t)i3 * 32 + lane];
            float2 v4 = bases2[(size_t)i4 * 32 + lane];
            float2 v5 = bases2[(size_t)i5 * 32 + lane];
            float2 v6 = bases2[(size_t)i6 * 32 + lane];
            float2 v7 = bases2[(size_t)i7 * 32 + lane];
            s.x += v0.x; s.y += v0.y;
            mx.x = fmaxf(mx.x, v0.x); mx.y = fmaxf(mx.y, v0.y);
            s.x += v1.x; s.y += v1.y;
            mx.x = fmaxf(mx.x, v1.x); mx.y = fmaxf(mx.y, v1.y);
            s.x += v2.x; s.y += v2.y;
            mx.x = fmaxf(mx.x, v2.x); mx.y = fmaxf(mx.y, v2.y);
            s.x += v3.x; s.y += v3.y;
            mx.x = fmaxf(mx.x, v3.x); mx.y = fmaxf(mx.y, v3.y);
            s.x += v4.x; s.y += v4.y;
            mx.x = fmaxf(mx.x, v4.x); mx.y = fmaxf(mx.y, v4.y);
            s.x += v5.x; s.y += v5.y;
            mx.x = fmaxf(mx.x, v5.x); mx.y = fmaxf(mx.y, v5.y);
            s.x += v6.x; s.y += v6.y;
            mx.x = fmaxf(mx.x, v6.x); mx.y = fmaxf(mx.y, v6.y);
            s.x += v7.x; s.y += v7.y;
            mx.x = fmaxf(mx.x, v7.x); mx.y = fmaxf(mx.y, v7.y);
        }
        for (; jj + 4 <= cnt; jj += 4){
            int i0 = __shfl_sync(0xffffffffu, myv, jj);
            int i1 = __shfl_sync(0xffffffffu, myv, jj + 1);
            int i2 = __shfl_sync(0xffffffffu, myv, jj + 2);
            int i3 = __shfl_sync(0xffffffffu, myv, jj + 3);
            float2 v0 = bases2[(size_t)i0 * 32 + lane];
            float2 v1 = bases2[(size_t)i1 * 32 + lane];
            float2 v2 = bases2[(size_t)i2 * 32 + lane];
            float2 v3 = bases2[(size_t)i3 * 32 + lane];
            s.x += v0.x; s.y += v0.y;
            mx.x = fmaxf(mx.x, v0.x); mx.y = fmaxf(mx.y, v0.y);
            s.x += v1.x; s.y += v1.y;
            mx.x = fmaxf(mx.x, v1.x); mx.y = fmaxf(mx.y, v1.y);
            s.x += v2.x; s.y += v2.y;
            mx.x = fmaxf(mx.x, v2.x); mx.y = fmaxf(mx.y, v2.y);
            s.x += v3.x; s.y += v3.y;
            mx.x = fmaxf(mx.x, v3.x); mx.y = fmaxf(mx.y, v3.y);
        }
        for (; jj < cnt; jj++){
            int sv = __shfl_sync(0xffffffffu, myv, jj);
            float2 v = bases2[(size_t)sv * 32 + lane];
            s.x += v.x; s.y += v.y;
            mx.x = fmaxf(mx.x, v.x); mx.y = fmaxf(mx.y, v.y);
        }
    }
    int deg = end - beg;
    float2 m;
    if (deg > 0){
        float inv = 1.f / (float)deg;
        m = make_float2(s.x * inv, s.y * inv);
    } else {
        m = make_float2(0.f, 0.f);
        mx = make_float2(0.f, 0.f);
    }
    __syncwarp();

    int b  = lane >> 3;
    int l8 = lane & 7;
    #pragma unroll
    for (int h = 0; h < 8; h++){
        float ws = wsm[ni][h * 12 + b];
        float wm = wsm[ni][h * 12 + 4 + b];
        float wx = wsm[ni][h * 12 + 8 + b];
        part2[ni][b][h * 8 + l8] = make_float2(ws * s.x + wm * m.x + wx * mx.x,
                                               ws * s.y + wm * m.y + wx * mx.y);
    }
    __syncwarp();

    const float2* convb2 = reinterpret_cast<const float2*>(convb);
    float2* gconv2 = reinterpret_cast<float2*>(gconv);
    #pragma unroll
    for (int c = lane; c < 64; c += 32){
        float2 p0 = part2[ni][0][c], p1 = part2[ni][1][c];
        float2 p2 = part2[ni][2][c], p3 = part2[ni][3][c];
        float2 cb = convb2[c];
        gconv2[(size_t)node * 64 + c] =
            make_float2(p0.x + p1.x + p2.x + p3.x + cb.x,
                        p0.y + p1.y + p2.y + p3.y + cb.y);
    }
}

// ---------------- GraphNorm: fused sum + sumsq (R9 exact) ----------------
__global__ void k_stats(const float* __restrict__ x, const int* __restrict__ gs,
                        float* __restrict__ gsum, float* __restrict__ gsq){
    int g = blockIdx.x, sp = blockIdx.y, S = gridDim.y;
    int beg = gs[g], end = gs[g + 1];
    int len = end - beg;
    int chunk = (len + S - 1) / S;
    int s0 = beg + sp * chunk;
    int s1 = min(s0 + chunk, end);
    if (s0 >= s1) return;
    int c = threadIdx.x;
    float a = 0.f, b = 0.f;
    for (int n = s0; n < s1; n++){
        float v = x[(size_t)n * 128 + c];
        a += v; b += v * v;
    }
    atomicAdd(&gsum[g * 128 + c], a);
    atomicAdd(&gsq[g * 128 + c], b);
}

// ---- norm: warp per node, float4 vectorized (R9 exact) ----
__global__ void __launch_bounds__(256) k_norm(
        float* __restrict__ h, const float* __restrict__ gc,
        const int* __restrict__ batch,
        const float* __restrict__ gsum, const float* __restrict__ gsq,
        const int* __restrict__ npg,
        const float* __restrict__ gnw, const float* __restrict__ gnb,
        const float* __restrict__ gnms){
    int tid = threadIdx.x;
    int node = blockIdx.x * 8 + (tid >> 5);
    int c = (tid & 31) * 4;
    if (node >= cfg::N) return;
    int g = __ldg(&batch[node]);
    float cnt = (float)max(npg[g], 1);
    float4 su = *reinterpret_cast<const float4*>(&gsum[g * 128 + c]);
    float4 sq = *reinterpret_cast<const float4*>(&gsq[g * 128 + c]);
    float4 ms = *reinterpret_cast<const float4*>(&gnms[c]);
    float4 wv = *reinterpret_cast<const float4*>(&gnw[c]);
    float4 bv = *reinterpret_cast<const float4*>(&gnb[c]);
    float4 gv = *reinterpret_cast<const float4*>(&gc[(size_t)node * 128 + c]);
    float4 hv = *reinterpret_cast<const float4*>(&h[(size_t)node * 128 + c]);
    float inv_cnt = 1.f / cnt;
    #pragma unroll
    for (int j = 0; j < 4; j++){
        float mu  = (&su.x)[j] * inv_cnt;
        float ex2 = (&sq.x)[j] * inv_cnt;
        float m   = (&ms.x)[j];
        float var = ex2 - mu * mu * m * (2.f - m);
        float inv = rsqrtf(fmaxf(var, 0.f) + cfg::EPS);
        float sub = (&gv.x)[j] - mu * m;
        float r = (&wv.x)[j] * sub * inv + (&bv.x)[j];
        (&hv.x)[j] += fmaxf(r, 0.f);
    }
    *reinterpret_cast<float4*>(&h[(size_t)node * 128 + c]) = hv;
}

__global__ void k_pool(const float* __restrict__ gsum, const int* __restrict__ npg,
                       float* __restrict__ y){
    int g = blockIdx.x, c = threadIdx.x;
    float cnt = (float)max(npg[g], 1);
    y[g * 128 + c] = gsum[g * 128 + c] / cnt;
}

// ---------------- launch ----------------
extern "C" void kernel_launch(void* const* d_in, const int* in_sizes, int n_in,
                              void* d_out, int out_size){
    using namespace cfg;
    const float* x      = (const float*)d_in[0];
    const int*   ei     = (const int*)  d_in[1];
    const int*   batch  = (const int*)  d_in[2];
    const int*   npg    = (const int*)  d_in[3];
    const float* lin_w  = (const float*)d_in[4];
    const float* lin_b  = (const float*)d_in[5];
    const float* basesw = (const float*)d_in[6];
    const float* combw  = (const float*)d_in[7];
    const float* combb  = (const float*)d_in[8];
    const float* convb  = (const float*)d_in[9];
    const float* gnw    = (const float*)d_in[10];
    const float* gnb    = (const float*)d_in[11];
    const float* gnms   = (const float*)d_in[12];

    float* h = (float*)d_out;
    float* y = h + (size_t)N * 128;

    void* sp = nullptr;
    cudaGetSymbolAddress(&sp, g_scratch);
    char* base = (char*)sp;
    int*   deg    = (int*)  (base + OFF_DEG);
    int*   cur    = (int*)  (base + OFF_CUR);
    int*   offs   = (int*)  (base + OFF_OFFS);
    int*   bsum   = (int*)  (base + OFF_BSUM);
    int*   csr    = (int*)  (base + OFF_CSR);
    int*   gst    = (int*)  (base + OFF_GST);
    float* basesF = (float*)(base + OFF_BASES);
    float* wF     = (float*)(base + OFF_W);
    float* gcF    = (float*)(base + OFF_GC);
    float* gsF    = (float*)(base + OFF_GS);
    float* gvF    = (float*)(base + OFF_GV);

    const int nb = (N + 1023) / 1024;
    constexpr int SMEM128 = 2 * 128 * 64 * 4;   // 65536
    constexpr int SMEM160 = 2 * 160 * 64 * 4;   // 81920

    cudaFuncSetAttribute(k_mma<128,128>, cudaFuncAttributeMaxDynamicSharedMemorySize, SMEM128);
    cudaFuncSetAttribute(k_mma<160,64>,  cudaFuncAttributeMaxDynamicSharedMemorySize, SMEM160);

    // lazily-created side stream + events (host resources; identical GPU work
    // each call, graph-capture fork/join via events)
    static cudaStream_t s1 = nullptr;
    static cudaEvent_t e0 = nullptr;
    static cudaEvent_t eR[LAYERS];               // norm(l) done (main)
    static cudaEvent_t eZ[LAYERS + 1];           // zero for layer l done (s1)
    if (!s1){
        cudaStreamCreateWithFlags(&s1, cudaStreamNonBlocking);
        cudaEventCreateWithFlags(&e0, cudaEventDisableTiming);
        for (int l = 0; l < LAYERS; l++)
            cudaEventCreateWithFlags(&eR[l], cudaEventDisableTiming);
        for (int l = 0; l <= LAYERS; l++)
            cudaEventCreateWithFlags(&eZ[l], cudaEventDisableTiming);
    }

    // ---- prologue: GEMMs on main stream, CSR build + first zero on s1 ----
    int zeroN = (int)(OFF_OFFS / 4);   // zeroes deg + cur (adjacent regions)
    k_mma<128,128><<<NT, 256, SMEM128>>>(x, N, lin_w, nullptr, lin_b, nullptr,
                                         h, nullptr);
    cudaEventRecord(e0, 0);
    cudaStreamWaitEvent(s1, e0, 0);
    k_zero<<<(zeroN + 255) / 256, 256, 0, s1>>>((unsigned int*)deg, zeroN);
    k_hist<<<(E + 255) / 256, 256, 0, s1>>>(ei, deg);
    k_mma<160,64><<<NT, 256, SMEM160>>>(                 // 4th launch (profiled)
        h, N, basesw, combw, nullptr, combb, basesF, wF);
    k_scan1<<<nb, 1024, 0, s1>>>(deg, offs, bsum);
    k_scan2<<<1, 128, 0, s1>>>(bsum, nb);
    k_scan3<<<(N + 255) / 256, 256, 0, s1>>>(offs, bsum);
    k_fill<<<(E + 255) / 256, 256, 0, s1>>>(ei, offs, cur, csr);
    k_gstart<<<1, 32, 0, s1>>>(npg, gst);
    k_zero<<<(2 * G * 128 + 255) / 256, 256, 0, s1>>>((unsigned int*)gsF, 2 * G * 128);
    cudaEventRecord(eZ[0], s1);
    cudaStreamWaitEvent(0, eZ[0], 0);

    // ---- layers: per-layer gsF zero overlapped on s1 ----
    for (int l = 0; l < LAYERS; l++){
        if (l > 0)
            k_mma<160,64><<<NT, 256, SMEM160>>>(
                h, N, basesw + (size_t)l * 128 * 64, combw + (size_t)l * 128 * 96,
                nullptr, combb + (size_t)l * 96, basesF, wF);
        k_agg<<<N / 8, 256>>>(basesF, wF, offs, csr, convb + (size_t)l * 128, gcF);
        if (l > 0) cudaStreamWaitEvent(0, eZ[l], 0);   // zero(gsF) done
        k_stats<<<dim3(G, 32), 128>>>(gcF, gst, gsF, gvF);
        k_norm<<<(N + 7) / 8, 256>>>(h, gcF, batch, gsF, gvF, npg,
                                     gnw + (size_t)l * 128, gnb + (size_t)l * 128,
                                     gnms + (size_t)l * 128);
        cudaEventRecord(eR[l], 0);
        cudaStreamWaitEvent(s1, eR[l], 0);             // gsF free after norm
        k_zero<<<(2 * G * 128 + 255) / 256, 256, 0, s1>>>((unsigned int*)gsF,
                                                          2 * G * 128);
        cudaEventRecord(eZ[l + 1], s1);
    }

    // ---- mean pool ----
    cudaStreamWaitEvent(0, eZ[LAYERS], 0);
    k_stats<<<dim3(G, 32), 128>>>(h, gst, gsF, gvF);
    k_pool<<<G, 128>>>(gsF, npg, y);
}

// round 16
// speedup vs baseline: 1.0389x; 1.0389x over previous
#include <cuda_runtime.h>
#include <cuda_bf16.h>
#include <cstdint>

// ---------------- problem constants ----------------
namespace cfg {
constexpr int N = 100000;
constexpr int E = 1600000;
constexpr int G = 64;
constexpr int LAYERS = 4;
constexpr float EPS = 1e-6f;
constexpr int NT = (N + 127) / 128;   // 782 row tiles

constexpr size_t aln(size_t x){ return (x + 255) & ~size_t(255); }
constexpr size_t OFF_DEG   = 0;
constexpr size_t OFF_CUR   = OFF_DEG   + aln(sizeof(int)*N);
constexpr size_t OFF_OFFS  = OFF_CUR   + aln(sizeof(int)*(size_t)N);
constexpr size_t OFF_BSUM  = OFF_OFFS  + aln(sizeof(int)*(size_t)(N+1));
constexpr size_t OFF_CSR   = OFF_BSUM  + aln(sizeof(int)*256);
constexpr size_t OFF_GST   = OFF_CSR   + aln(sizeof(int)*(size_t)E);
constexpr size_t OFF_BASES = OFF_GST   + aln(sizeof(int)*(G+1));
constexpr size_t OFF_W     = OFF_BASES + aln(sizeof(float)*(size_t)N*64);
constexpr size_t OFF_GC    = OFF_W     + aln(sizeof(float)*(size_t)N*96);
constexpr size_t OFF_GS    = OFF_GC    + aln(sizeof(float)*(size_t)N*128);
constexpr size_t OFF_GV    = OFF_GS    + aln(sizeof(float)*(size_t)G*128);
constexpr size_t TOTAL     = OFF_GV    + aln(sizeof(float)*(size_t)G*128);
}

__device__ __align__(256) unsigned char g_scratch[cfg::TOTAL];

// ---------------- mma helpers ----------------
__device__ __forceinline__ uint32_t bf2_u32(__nv_bfloat162 v){
    return *reinterpret_cast<uint32_t*>(&v);
}
__device__ __forceinline__ void mma_bf16(float* c, const uint32_t* a, uint32_t b0, uint32_t b1){
    asm volatile(
        "mma.sync.aligned.m16n8k16.row.col.f32.bf16.bf16.f32 "
        "{%0,%1,%2,%3}, {%4,%5,%6,%7}, {%8,%9}, {%0,%1,%2,%3};"
        : "+f"(c[0]), "+f"(c[1]), "+f"(c[2]), "+f"(c[3])
        : "r"(a[0]), "r"(a[1]), "r"(a[2]), "r"(a[3]), "r"(b0), "r"(b1));
}
__device__ __forceinline__ void split_bf16(float2 v, uint32_t& hi, uint32_t& lo){
    __nv_bfloat162 h2 = __floats2bfloat162_rn(v.x, v.y);
    __nv_bfloat162 l2 = __floats2bfloat162_rn(v.x - __low2float(h2),
                                              v.y - __high2float(h2));
    hi = bf2_u32(h2); lo = bf2_u32(l2);
}

// ---------------- small utility kernels ----------------
__global__ void k_zero(unsigned int* __restrict__ p, int n){
    int i = blockIdx.x * blockDim.x + threadIdx.x;
    if (i < n) p[i] = 0u;
}
__global__ void k_hist(const int* __restrict__ ei, int* __restrict__ deg){
    int e = blockIdx.x * blockDim.x + threadIdx.x;
    if (e < cfg::E) atomicAdd(&deg[ei[cfg::E + e]], 1);
}
__global__ void k_scan1(const int* __restrict__ deg, int* __restrict__ offs,
                        int* __restrict__ bsum){
    __shared__ int sm[1024];
    int tid = threadIdx.x;
    int i = blockIdx.x * 1024 + tid;
    int v = (i < cfg::N) ? deg[i] : 0;
    sm[tid] = v; __syncthreads();
    for (int d = 1; d < 1024; d <<= 1){
        int t = (tid >= d) ? sm[tid - d] : 0;
        __syncthreads(); sm[tid] += t; __syncthreads();
    }
    if (i < cfg::N) offs[i + 1] = sm[tid];
    if (tid == 1023) bsum[blockIdx.x] = sm[1023];
}
__global__ void k_scan2(int* __restrict__ bsum, int nb){
    __shared__ int sm[128];
    int tid = threadIdx.x;
    int v = (tid < nb) ? bsum[tid] : 0;
    sm[tid] = v; __syncthreads();
    for (int d = 1; d < 128; d <<= 1){
        int t = (tid >= d) ? sm[tid - d] : 0;
        __syncthreads(); sm[tid] += t; __syncthreads();
    }
    if (tid < nb) bsum[tid] = sm[tid] - v;
}
__global__ void k_scan3(int* __restrict__ offs, const int* __restrict__ bsum){
    int i = blockIdx.x * blockDim.x + threadIdx.x;
    if (i < cfg::N) offs[i + 1] += bsum[i >> 10];
    if (i == 0) offs[0] = 0;
}
__global__ void k_fill(const int* __restrict__ ei, const int* __restrict__ offs,
                       int* __restrict__ cur, int* __restrict__ csr){
    int e = blockIdx.x * blockDim.x + threadIdx.x;
    if (e < cfg::E){
        int d = ei[cfg::E + e];
        int pos = offs[d] + atomicAdd(&cur[d], 1);
        csr[pos] = ei[e];
    }
}
__global__ void k_gstart(const int* __restrict__ npg, int* __restrict__ gs){
    if (blockIdx.x == 0 && threadIdx.x == 0){
        int run = 0;
        for (int g = 0; g < cfg::G; g++){ gs[g] = run; run += npg[g]; }
        gs[cfg::G] = run;
    }
}

// ------ bf16 3-pass GEMM via mma.sync m16n8k16: [M,128] @ [128,NOUT] ------
// R5/R9 configuration (best measured): full NOUT per CTA, A fragments from
// global with 2-deep prefetch, B in smem as separate hi/lo arrays. 2 CTAs/SM.
template<int NOUT, int S0>
__global__ void __launch_bounds__(256, 2)
k_mma(const float* __restrict__ A, int M,
      const float* __restrict__ W0, const float* __restrict__ W1,
      const float* __restrict__ bias0, const float* __restrict__ bias1,
      float* __restrict__ out0, float* __restrict__ out1){
    constexpr int S1  = NOUT - S0;
    constexpr int NT8 = NOUT / 8;
    extern __shared__ uint32_t smu[];
    uint32_t* Bhi = smu;                      // [NOUT][64] packed bf16x2
    uint32_t* Blo = Bhi + NOUT * 64;

    int tid = threadIdx.x;
    int w = tid >> 5, lane = tid & 31;
    int row0 = blockIdx.x * 128;

    // ---- stage B hi/lo: Bcol[n][p], swizzle p ^= (n&7)<<2 ----
    #pragma unroll 2
    for (int idx = tid; idx < 64 * S0; idx += 256){
        int p = idx / S0, n = idx - p * S0;
        float f0 = W0[(size_t)(2 * p) * S0 + n];
        float f1 = W0[(size_t)(2 * p + 1) * S0 + n];
        uint32_t hi, lo;
        split_bf16(make_float2(f0, f1), hi, lo);
        int pos = n * 64 + (p ^ ((n & 7) << 2));
        Bhi[pos] = hi; Blo[pos] = lo;
    }
    if constexpr (S1 > 0){
        #pragma unroll 2
        for (int idx = tid; idx < 64 * S1; idx += 256){
            int p = idx / S1, n = idx - p * S1;
            float f0 = W1[(size_t)(2 * p) * S1 + n];
            float f1 = W1[(size_t)(2 * p + 1) * S1 + n];
            uint32_t hi, lo;
            split_bf16(make_float2(f0, f1), hi, lo);
            int nn = S0 + n;
            int pos = nn * 64 + (p ^ ((nn & 7) << 2));
            Bhi[pos] = hi; Blo[pos] = lo;
        }
    }
    __syncthreads();

    float acc[NT8][4];
    #pragma unroll
    for (int t = 0; t < NT8; t++)
        #pragma unroll
        for (int j = 0; j < 4; j++) acc[t][j] = 0.f;

    int l4 = lane & 3, g = lane >> 2;
    int r1 = w * 16 + g;
    int gr1 = row0 + r1, gr2 = gr1 + 8;
    int cr1 = min(gr1, M - 1), cr2 = min(gr2, M - 1);
    const float2* pA1 = reinterpret_cast<const float2*>(A) + (size_t)cr1 * 64 + l4;
    const float2* pA2 = reinterpret_cast<const float2*>(A) + (size_t)cr2 * 64 + l4;

    // 2-deep ping-pong prefetch of A fragments
    float2 xb[2][4];
    #pragma unroll
    for (int j = 0; j < 2; j++){
        xb[j][0] = pA1[j * 8];     xb[j][1] = pA2[j * 8];
        xb[j][2] = pA1[j * 8 + 4]; xb[j][3] = pA2[j * 8 + 4];
    }
    int swz = g << 2;

    #pragma unroll
    for (int k0 = 0; k0 < 8; k0++){            // k-pair base = k0*8 (16 floats)
        uint32_t ah[4], al[4];
        split_bf16(xb[k0 & 1][0], ah[0], al[0]);
        split_bf16(xb[k0 & 1][1], ah[1], al[1]);
        split_bf16(xb[k0 & 1][2], ah[2], al[2]);
        split_bf16(xb[k0 & 1][3], ah[3], al[3]);
        if (k0 < 6){
            xb[k0 & 1][0] = pA1[(k0 + 2) * 8];     xb[k0 & 1][1] = pA2[(k0 + 2) * 8];
            xb[k0 & 1][2] = pA1[(k0 + 2) * 8 + 4]; xb[k0 & 1][3] = pA2[(k0 + 2) * 8 + 4];
        }
        int c0 = (k0 * 8 + l4) ^ swz;
        int c1 = (k0 * 8 + 4 + l4) ^ swz;
        #pragma unroll
        for (int nt = 0; nt < NT8; nt++){
            int nb = (nt * 8 + g) * 64;
            uint32_t bh0 = Bhi[nb + c0], bh1 = Bhi[nb + c1];
            uint32_t bl0 = Blo[nb + c0], bl1 = Blo[nb + c1];
            mma_bf16(acc[nt], ah, bh0, bh1);
            mma_bf16(acc[nt], ah, bl0, bl1);
            mma_bf16(acc[nt], al, bh0, bh1);
        }
    }

    // ---- epilogue ----
    #pragma unroll
    for (int nt = 0; nt < NT8; nt++){
        int col = nt * 8 + 2 * l4;
        float b0 = 0.f, b1 = 0.f;
        float* o;
        int width, oc;
        if (nt * 8 < S0){
            o = out0; width = S0; oc = col;
            if (bias0){ b0 = bias0[oc]; b1 = bias0[oc + 1]; }
        } else {
            o = out1; width = S1; oc = col - S0;
            if (bias1){ b0 = bias1[oc]; b1 = bias1[oc + 1]; }
        }
        if (gr1 < M)
            *reinterpret_cast<float2*>(&o[(size_t)gr1 * width + oc]) =
                make_float2(acc[nt][0] + b0, acc[nt][1] + b1);
        if (gr2 < M)
            *reinterpret_cast<float2*>(&o[(size_t)gr2 * width + oc]) =
                make_float2(acc[nt][2] + b0, acc[nt][3] + b1);
    }
}

// ---- fused aggregate (sum/mean/max over CSR) + combine ----
// One warp per node; shfl-based index distribution; 4-wide MLP.
// Measured-best configuration (R9).
__global__ void __launch_bounds__(256) k_agg(
        const float* __restrict__ bases, const float* __restrict__ wmat,
        const int* __restrict__ offs, const int* __restrict__ csr,
        const float* __restrict__ convb, float* __restrict__ gconv){
    __shared__ float  wsm[8][96];
    __shared__ float2 part2[8][4][66];
    int tid = threadIdx.x;
    int ni = tid >> 5;
    int lane = tid & 31;
    int node = blockIdx.x * 8 + ni;

    for (int i = lane; i < 96; i += 32) wsm[ni][i] = wmat[(size_t)node * 96 + i];

    int beg = offs[node], end = offs[node + 1];
    const float2* bases2 = reinterpret_cast<const float2*>(bases);
    float ninf = __int_as_float(0xff800000);
    float2 s  = make_float2(0.f, 0.f);
    float2 mx = make_float2(ninf, ninf);

    for (int j0 = beg; j0 < end; j0 += 32){
        int myv = (j0 + lane < end) ? csr[j0 + lane] : 0;
        int cnt = min(32, end - j0);
        int jj = 0;
        for (; jj + 4 <= cnt; jj += 4){
            int s0 = __shfl_sync(0xffffffffu, myv, jj);
            int s1 = __shfl_sync(0xffffffffu, myv, jj + 1);
            int s2 = __shfl_sync(0xffffffffu, myv, jj + 2);
            int s3 = __shfl_sync(0xffffffffu, myv, jj + 3);
            float2 v0 = bases2[(size_t)s0 * 32 + lane];
            float2 v1 = bases2[(size_t)s1 * 32 + lane];
            float2 v2 = bases2[(size_t)s2 * 32 + lane];
            float2 v3 = bases2[(size_t)s3 * 32 + lane];
            s.x += v0.x; s.y += v0.y;
            mx.x = fmaxf(mx.x, v0.x); mx.y = fmaxf(mx.y, v0.y);
            s.x += v1.x; s.y += v1.y;
            mx.x = fmaxf(mx.x, v1.x); mx.y = fmaxf(mx.y, v1.y);
            s.x += v2.x; s.y += v2.y;
            mx.x = fmaxf(mx.x, v2.x); mx.y = fmaxf(mx.y, v2.y);
            s.x += v3.x; s.y += v3.y;
            mx.x = fmaxf(mx.x, v3.x); mx.y = fmaxf(mx.y, v3.y);
        }
        for (; jj < cnt; jj++){
            int sv = __shfl_sync(0xffffffffu, myv, jj);
            float2 v = bases2[(size_t)sv * 32 + lane];
            s.x += v.x; s.y += v.y;
            mx.x = fmaxf(mx.x, v.x); mx.y = fmaxf(mx.y, v.y);
        }
    }
    int deg = end - beg;
    float2 m;
    if (deg > 0){
        float inv = 1.f / (float)deg;
        m = make_float2(s.x * inv, s.y * inv);
    } else {
        m = make_float2(0.f, 0.f);
        mx = make_float2(0.f, 0.f);
    }
    __syncwarp();

    int b  = lane >> 3;
    int l8 = lane & 7;
    #pragma unroll
    for (int h = 0; h < 8; h++){
        float ws = wsm[ni][h * 12 + b];
        float wm = wsm[ni][h * 12 + 4 + b];
        float wx = wsm[ni][h * 12 + 8 + b];
        part2[ni][b][h * 8 + l8] = make_float2(ws * s.x + wm * m.x + wx * mx.x,
                                               ws * s.y + wm * m.y + wx * mx.y);
    }
    __syncwarp();

    const float2* convb2 = reinterpret_cast<const float2*>(convb);
    float2* gconv2 = reinterpret_cast<float2*>(gconv);
    #pragma unroll
    for (int c = lane; c < 64; c += 32){
        float2 p0 = part2[ni][0][c], p1 = part2[ni][1][c];
        float2 p2 = part2[ni][2][c], p3 = part2[ni][3][c];
        float2 cb = convb2[c];
        gconv2[(size_t)node * 64 + c] =
            make_float2(p0.x + p1.x + p2.x + p3.x + cb.x,
                        p0.y + p1.y + p2.y + p3.y + cb.y);
    }
}

// ---------------- GraphNorm: fused sum + sumsq ----------------
__global__ void k_stats(const float* __restrict__ x, const int* __restrict__ gs,
                        float* __restrict__ gsum, float* __restrict__ gsq){
    int g = blockIdx.x, sp = blockIdx.y, S = gridDim.y;
    int beg = gs[g], end = gs[g + 1];
    int len = end - beg;
    int chunk = (len + S - 1) / S;
    int s0 = beg + sp * chunk;
    int s1 = min(s0 + chunk, end);
    if (s0 >= s1) return;
    int c = threadIdx.x;
    float a = 0.f, b = 0.f;
    for (int n = s0; n < s1; n++){
        float v = x[(size_t)n * 128 + c];
        a += v; b += v * v;
    }
    atomicAdd(&gsum[g * 128 + c], a);
    atomicAdd(&gsq[g * 128 + c], b);
}

// ---- norm: warp per node, float4 vectorized ----
__global__ void __launch_bounds__(256) k_norm(
        float* __restrict__ h, const float* __restrict__ gc,
        const int* __restrict__ batch,
        const float* __restrict__ gsum, const float* __restrict__ gsq,
        const int* __restrict__ npg,
        const float* __restrict__ gnw, const float* __restrict__ gnb,
        const float* __restrict__ gnms){
    int tid = threadIdx.x;
    int node = blockIdx.x * 8 + (tid >> 5);
    int c = (tid & 31) * 4;
    if (node >= cfg::N) return;
    int g = __ldg(&batch[node]);
    float cnt = (float)max(npg[g], 1);
    float4 su = *reinterpret_cast<const float4*>(&gsum[g * 128 + c]);
    float4 sq = *reinterpret_cast<const float4*>(&gsq[g * 128 + c]);
    float4 ms = *reinterpret_cast<const float4*>(&gnms[c]);
    float4 wv = *reinterpret_cast<const float4*>(&gnw[c]);
    float4 bv = *reinterpret_cast<const float4*>(&gnb[c]);
    float4 gv = *reinterpret_cast<const float4*>(&gc[(size_t)node * 128 + c]);
    float4 hv = *reinterpret_cast<const float4*>(&h[(size_t)node * 128 + c]);
    float inv_cnt = 1.f / cnt;
    #pragma unroll
    for (int j = 0; j < 4; j++){
        float mu  = (&su.x)[j] * inv_cnt;
        float ex2 = (&sq.x)[j] * inv_cnt;
        float m   = (&ms.x)[j];
        float var = ex2 - mu * mu * m * (2.f - m);
        float inv = rsqrtf(fmaxf(var, 0.f) + cfg::EPS);
        float sub = (&gv.x)[j] - mu * m;
        float r = (&wv.x)[j] * sub * inv + (&bv.x)[j];
        (&hv.x)[j] += fmaxf(r, 0.f);
    }
    *reinterpret_cast<float4*>(&h[(size_t)node * 128 + c]) = hv;
}

__global__ void k_pool(const float* __restrict__ gsum, const int* __restrict__ npg,
                       float* __restrict__ y){
    int g = blockIdx.x, c = threadIdx.x;
    float cnt = (float)max(npg[g], 1);
    y[g * 128 + c] = gsum[g * 128 + c] / cnt;
}

// ---------------- launch ----------------
extern "C" void kernel_launch(void* const* d_in, const int* in_sizes, int n_in,
                              void* d_out, int out_size){
    using namespace cfg;
    const float* x      = (const float*)d_in[0];
    const int*   ei     = (const int*)  d_in[1];
    const int*   batch  = (const int*)  d_in[2];
    const int*   npg    = (const int*)  d_in[3];
    const float* lin_w  = (const float*)d_in[4];
    const float* lin_b  = (const float*)d_in[5];
    const float* basesw = (const float*)d_in[6];
    const float* combw  = (const float*)d_in[7];
    const float* combb  = (const float*)d_in[8];
    const float* convb  = (const float*)d_in[9];
    const float* gnw    = (const float*)d_in[10];
    const float* gnb    = (const float*)d_in[11];
    const float* gnms   = (const float*)d_in[12];

    float* h = (float*)d_out;
    float* y = h + (size_t)N * 128;

    void* sp = nullptr;
    cudaGetSymbolAddress(&sp, g_scratch);
    char* base = (char*)sp;
    int*   deg    = (int*)  (base + OFF_DEG);
    int*   cur    = (int*)  (base + OFF_CUR);
    int*   offs   = (int*)  (base + OFF_OFFS);
    int*   bsum   = (int*)  (base + OFF_BSUM);
    int*   csr    = (int*)  (base + OFF_CSR);
    int*   gst    = (int*)  (base + OFF_GST);
    float* basesF = (float*)(base + OFF_BASES);
    float* wF     = (float*)(base + OFF_W);
    float* gcF    = (float*)(base + OFF_GC);
    float* gsF    = (float*)(base + OFF_GS);
    float* gvF    = (float*)(base + OFF_GV);

    const int nb = (N + 1023) / 1024;
    constexpr int SMEM128 = 2 * 128 * 64 * 4;   // 65536
    constexpr int SMEM160 = 2 * 160 * 64 * 4;   // 81920

    cudaFuncSetAttribute(k_mma<128,128>, cudaFuncAttributeMaxDynamicSharedMemorySize, SMEM128);
    cudaFuncSetAttribute(k_mma<160,64>,  cudaFuncAttributeMaxDynamicSharedMemorySize, SMEM160);

    // lazily-created side stream + events (host resources; identical GPU work
    // each call, graph-capture fork/join via events)
    static cudaStream_t s1 = nullptr;
    static cudaEvent_t e0 = nullptr;
    static cudaEvent_t eR[LAYERS];               // norm(l) done (main)
    static cudaEvent_t eZ[LAYERS + 1];           // zero for layer l done (s1)
    if (!s1){
        cudaStreamCreateWithFlags(&s1, cudaStreamNonBlocking);
        cudaEventCreateWithFlags(&e0, cudaEventDisableTiming);
        for (int l = 0; l < LAYERS; l++)
            cudaEventCreateWithFlags(&eR[l], cudaEventDisableTiming);
        for (int l = 0; l <= LAYERS; l++)
            cudaEventCreateWithFlags(&eZ[l], cudaEventDisableTiming);
    }

    // ---- prologue: GEMMs on main stream, CSR build + first zero on s1 ----
    int zeroN = (int)(OFF_OFFS / 4);   // zeroes deg + cur (adjacent regions)
    k_mma<128,128><<<NT, 256, SMEM128>>>(x, N, lin_w, nullptr, lin_b, nullptr,
                                         h, nullptr);
    cudaEventRecord(e0, 0);
    cudaStreamWaitEvent(s1, e0, 0);
    k_zero<<<(zeroN + 255) / 256, 256, 0, s1>>>((unsigned int*)deg, zeroN);
    k_hist<<<(E + 255) / 256, 256, 0, s1>>>(ei, deg);
    k_mma<160,64><<<NT, 256, SMEM160>>>(                 // 4th launch (profiled)
        h, N, basesw, combw, nullptr, combb, basesF, wF);
    k_scan1<<<nb, 1024, 0, s1>>>(deg, offs, bsum);
    k_scan2<<<1, 128, 0, s1>>>(bsum, nb);
    k_scan3<<<(N + 255) / 256, 256, 0, s1>>>(offs, bsum);
    k_fill<<<(E + 255) / 256, 256, 0, s1>>>(ei, offs, cur, csr);
    k_gstart<<<1, 32, 0, s1>>>(npg, gst);
    k_zero<<<(2 * G * 128 + 255) / 256, 256, 0, s1>>>((unsigned int*)gsF, 2 * G * 128);
    cudaEventRecord(eZ[0], s1);
    cudaStreamWaitEvent(0, eZ[0], 0);

    // ---- layers: per-layer gsF zero overlapped on s1 ----
    for (int l = 0; l < LAYERS; l++){
        if (l > 0)
            k_mma<160,64><<<NT, 256, SMEM160>>>(
                h, N, basesw + (size_t)l * 128 * 64, combw + (size_t)l * 128 * 96,
                nullptr, combb + (size_t)l * 96, basesF, wF);
        k_agg<<<N / 8, 256>>>(basesF, wF, offs, csr, convb + (size_t)l * 128, gcF);
        if (l > 0) cudaStreamWaitEvent(0, eZ[l], 0);   // zero(gsF) done
        k_stats<<<dim3(G, 32), 128>>>(gcF, gst, gsF, gvF);
        k_norm<<<(N + 7) / 8, 256>>>(h, gcF, batch, gsF, gvF, npg,
                                     gnw + (size_t)l * 128, gnb + (size_t)l * 128,
                                     gnms + (size_t)l * 128);
        cudaEventRecord(eR[l], 0);
        cudaStreamWaitEvent(s1, eR[l], 0);             // gsF free after norm
        k_zero<<<(2 * G * 128 + 255) / 256, 256, 0, s1>>>((unsigned int*)gsF,
                                                          2 * G * 128);
        cudaEventRecord(eZ[l + 1], s1);
    }

    // ---- mean pool ----
    cudaStreamWaitEvent(0, eZ[LAYERS], 0);
    k_stats<<<dim3(G, 32), 128>>>(h, gst, gsF, gvF);
    k_pool<<<G, 128>>>(gsF, npg, y);
}

// round 17
// speedup vs baseline: 1.0746x; 1.0343x over previous
#include <cuda_runtime.h>
#include <cuda_bf16.h>
#include <cuda_fp16.h>
#include <cstdint>

// ---------------- problem constants ----------------
namespace cfg {
constexpr int N = 100000;
constexpr int E = 1600000;
constexpr int G = 64;
constexpr int LAYERS = 4;
constexpr float EPS = 1e-6f;
constexpr int NT = (N + 127) / 128;   // 782 row tiles

constexpr size_t aln(size_t x){ return (x + 255) & ~size_t(255); }
constexpr size_t OFF_DEG   = 0;
constexpr size_t OFF_CUR   = OFF_DEG   + aln(sizeof(int)*N);
constexpr size_t OFF_OFFS  = OFF_CUR   + aln(sizeof(int)*(size_t)N);
constexpr size_t OFF_BSUM  = OFF_OFFS  + aln(sizeof(int)*(size_t)(N+1));
constexpr size_t OFF_CSR   = OFF_BSUM  + aln(sizeof(int)*256);
constexpr size_t OFF_GST   = OFF_CSR   + aln(sizeof(int)*(size_t)E);
constexpr size_t OFF_BASES = OFF_GST   + aln(sizeof(int)*(G+1));
constexpr size_t OFF_W     = OFF_BASES + aln(sizeof(float)*(size_t)N*64);  // half now, keep slot
constexpr size_t OFF_GC    = OFF_W     + aln(sizeof(float)*(size_t)N*96);
constexpr size_t OFF_GS    = OFF_GC    + aln(sizeof(float)*(size_t)N*128);
constexpr size_t OFF_GV    = OFF_GS    + aln(sizeof(float)*(size_t)G*128);
constexpr size_t TOTAL     = OFF_GV    + aln(sizeof(float)*(size_t)G*128);
}

__device__ __align__(256) unsigned char g_scratch[cfg::TOTAL];

// ---------------- mma helpers ----------------
__device__ __forceinline__ uint32_t bf2_u32(__nv_bfloat162 v){
    return *reinterpret_cast<uint32_t*>(&v);
}
__device__ __forceinline__ void mma_bf16(float* c, const uint32_t* a, uint32_t b0, uint32_t b1){
    asm volatile(
        "mma.sync.aligned.m16n8k16.row.col.f32.bf16.bf16.f32 "
        "{%0,%1,%2,%3}, {%4,%5,%6,%7}, {%8,%9}, {%0,%1,%2,%3};"
        : "+f"(c[0]), "+f"(c[1]), "+f"(c[2]), "+f"(c[3])
        : "r"(a[0]), "r"(a[1]), "r"(a[2]), "r"(a[3]), "r"(b0), "r"(b1));
}
__device__ __forceinline__ void split_bf16(float2 v, uint32_t& hi, uint32_t& lo){
    __nv_bfloat162 h2 = __floats2bfloat162_rn(v.x, v.y);
    __nv_bfloat162 l2 = __floats2bfloat162_rn(v.x - __low2float(h2),
                                              v.y - __high2float(h2));
    hi = bf2_u32(h2); lo = bf2_u32(l2);
}

// ---------------- small utility kernels ----------------
__global__ void k_zero(unsigned int* __restrict__ p, int n){
    int i = blockIdx.x * blockDim.x + threadIdx.x;
    if (i < n) p[i] = 0u;
}
__global__ void k_hist(const int* __restrict__ ei, int* __restrict__ deg){
    int e = blockIdx.x * blockDim.x + threadIdx.x;
    if (e < cfg::E) atomicAdd(&deg[ei[cfg::E + e]], 1);
}
__global__ void k_scan1(const int* __restrict__ deg, int* __restrict__ offs,
                        int* __restrict__ bsum){
    __shared__ int sm[1024];
    int tid = threadIdx.x;
    int i = blockIdx.x * 1024 + tid;
    int v = (i < cfg::N) ? deg[i] : 0;
    sm[tid] = v; __syncthreads();
    for (int d = 1; d < 1024; d <<= 1){
        int t = (tid >= d) ? sm[tid - d] : 0;
        __syncthreads(); sm[tid] += t; __syncthreads();
    }
    if (i < cfg::N) offs[i + 1] = sm[tid];
    if (tid == 1023) bsum[blockIdx.x] = sm[1023];
}
__global__ void k_scan2(int* __restrict__ bsum, int nb){
    __shared__ int sm[128];
    int tid = threadIdx.x;
    int v = (tid < nb) ? bsum[tid] : 0;
    sm[tid] = v; __syncthreads();
    for (int d = 1; d < 128; d <<= 1){
        int t = (tid >= d) ? sm[tid - d] : 0;
        __syncthreads(); sm[tid] += t; __syncthreads();
    }
    if (tid < nb) bsum[tid] = sm[tid] - v;
}
__global__ void k_scan3(int* __restrict__ offs, const int* __restrict__ bsum){
    int i = blockIdx.x * blockDim.x + threadIdx.x;
    if (i < cfg::N) offs[i + 1] += bsum[i >> 10];
    if (i == 0) offs[0] = 0;
}
__global__ void k_fill(const int* __restrict__ ei, const int* __restrict__ offs,
                       int* __restrict__ cur, int* __restrict__ csr){
    int e = blockIdx.x * blockDim.x + threadIdx.x;
    if (e < cfg::E){
        int d = ei[cfg::E + e];
        int pos = offs[d] + atomicAdd(&cur[d], 1);
        csr[pos] = ei[e];
    }
}
__global__ void k_gstart(const int* __restrict__ npg, int* __restrict__ gs){
    if (blockIdx.x == 0 && threadIdx.x == 0){
        int run = 0;
        for (int g = 0; g < cfg::G; g++){ gs[g] = run; run += npg[g]; }
        gs[cfg::G] = run;
    }
}

// ------ bf16 3-pass GEMM via mma.sync m16n8k16: [M,128] @ [128,NOUT] ------
// R9 configuration. HALF0: store out0 columns as fp16 (bases gather operand).
template<int NOUT, int S0, int HALF0>
__global__ void __launch_bounds__(256, 2)
k_mma(const float* __restrict__ A, int M,
      const float* __restrict__ W0, const float* __restrict__ W1,
      const float* __restrict__ bias0, const float* __restrict__ bias1,
      float* __restrict__ out0, float* __restrict__ out1){
    constexpr int S1  = NOUT - S0;
    constexpr int NT8 = NOUT / 8;
    extern __shared__ uint32_t smu[];
    uint32_t* Bhi = smu;                      // [NOUT][64] packed bf16x2
    uint32_t* Blo = Bhi + NOUT * 64;

    int tid = threadIdx.x;
    int w = tid >> 5, lane = tid & 31;
    int row0 = blockIdx.x * 128;

    // ---- stage B hi/lo: Bcol[n][p], swizzle p ^= (n&7)<<2 ----
    #pragma unroll 2
    for (int idx = tid; idx < 64 * S0; idx += 256){
        int p = idx / S0, n = idx - p * S0;
        float f0 = W0[(size_t)(2 * p) * S0 + n];
        float f1 = W0[(size_t)(2 * p + 1) * S0 + n];
        uint32_t hi, lo;
        split_bf16(make_float2(f0, f1), hi, lo);
        int pos = n * 64 + (p ^ ((n & 7) << 2));
        Bhi[pos] = hi; Blo[pos] = lo;
    }
    if constexpr (S1 > 0){
        #pragma unroll 2
        for (int idx = tid; idx < 64 * S1; idx += 256){
            int p = idx / S1, n = idx - p * S1;
            float f0 = W1[(size_t)(2 * p) * S1 + n];
            float f1 = W1[(size_t)(2 * p + 1) * S1 + n];
            uint32_t hi, lo;
            split_bf16(make_float2(f0, f1), hi, lo);
            int nn = S0 + n;
            int pos = nn * 64 + (p ^ ((nn & 7) << 2));
            Bhi[pos] = hi; Blo[pos] = lo;
        }
    }
    __syncthreads();

    float acc[NT8][4];
    #pragma unroll
    for (int t = 0; t < NT8; t++)
        #pragma unroll
        for (int j = 0; j < 4; j++) acc[t][j] = 0.f;

    int l4 = lane & 3, g = lane >> 2;
    int r1 = w * 16 + g;
    int gr1 = row0 + r1, gr2 = gr1 + 8;
    int cr1 = min(gr1, M - 1), cr2 = min(gr2, M - 1);
    const float2* pA1 = reinterpret_cast<const float2*>(A) + (size_t)cr1 * 64 + l4;
    const float2* pA2 = reinterpret_cast<const float2*>(A) + (size_t)cr2 * 64 + l4;

    // 2-deep ping-pong prefetch of A fragments
    float2 xb[2][4];
    #pragma unroll
    for (int j = 0; j < 2; j++){
        xb[j][0] = pA1[j * 8];     xb[j][1] = pA2[j * 8];
        xb[j][2] = pA1[j * 8 + 4]; xb[j][3] = pA2[j * 8 + 4];
    }
    int swz = g << 2;

    #pragma unroll
    for (int k0 = 0; k0 < 8; k0++){            // k-pair base = k0*8 (16 floats)
        uint32_t ah[4], al[4];
        split_bf16(xb[k0 & 1][0], ah[0], al[0]);
        split_bf16(xb[k0 & 1][1], ah[1], al[1]);
        split_bf16(xb[k0 & 1][2], ah[2], al[2]);
        split_bf16(xb[k0 & 1][3], ah[3], al[3]);
        if (k0 < 6){
            xb[k0 & 1][0] = pA1[(k0 + 2) * 8];     xb[k0 & 1][1] = pA2[(k0 + 2) * 8];
            xb[k0 & 1][2] = pA1[(k0 + 2) * 8 + 4]; xb[k0 & 1][3] = pA2[(k0 + 2) * 8 + 4];
        }
        int c0 = (k0 * 8 + l4) ^ swz;
        int c1 = (k0 * 8 + 4 + l4) ^ swz;
        #pragma unroll
        for (int nt = 0; nt < NT8; nt++){
            int nb = (nt * 8 + g) * 64;
            uint32_t bh0 = Bhi[nb + c0], bh1 = Bhi[nb + c1];
            uint32_t bl0 = Blo[nb + c0], bl1 = Blo[nb + c1];
            mma_bf16(acc[nt], ah, bh0, bh1);
            mma_bf16(acc[nt], ah, bl0, bl1);
            mma_bf16(acc[nt], al, bh0, bh1);
        }
    }

    // ---- epilogue ----
    #pragma unroll
    for (int nt = 0; nt < NT8; nt++){
        int col = nt * 8 + 2 * l4;
        if (HALF0 && nt * 8 < S0){
            // bases: store fp16 (no bias)
            __half* o = reinterpret_cast<__half*>(out0);
            if (gr1 < M)
                *reinterpret_cast<__half2*>(&o[(size_t)gr1 * S0 + col]) =
                    __floats2half2_rn(acc[nt][0], acc[nt][1]);
            if (gr2 < M)
                *reinterpret_cast<__half2*>(&o[(size_t)gr2 * S0 + col]) =
                    __floats2half2_rn(acc[nt][2], acc[nt][3]);
            continue;
        }
        float b0 = 0.f, b1 = 0.f;
        float* o;
        int width, oc;
        if (nt * 8 < S0){
            o = out0; width = S0; oc = col;
            if (bias0){ b0 = bias0[oc]; b1 = bias0[oc + 1]; }
        } else {
            o = out1; width = S1; oc = col - S0;
            if (bias1){ b0 = bias1[oc]; b1 = bias1[oc + 1]; }
        }
        if (gr1 < M)
            *reinterpret_cast<float2*>(&o[(size_t)gr1 * width + oc]) =
                make_float2(acc[nt][0] + b0, acc[nt][1] + b1);
        if (gr2 < M)
            *reinterpret_cast<float2*>(&o[(size_t)gr2 * width + oc]) =
                make_float2(acc[nt][2] + b0, acc[nt][3] + b1);
    }
}

// ---- fused aggregate (sum/mean/max over CSR) + combine ----
// One warp per node; shfl index distribution; 4-wide MLP (R9 structure).
// ONLY change: bases gathered as fp16 (half the L2 traffic), accumulated fp32.
__global__ void __launch_bounds__(256) k_agg(
        const __half2* __restrict__ basesH, const float* __restrict__ wmat,
        const int* __restrict__ offs, const int* __restrict__ csr,
        const float* __restrict__ convb, float* __restrict__ gconv){
    __shared__ float  wsm[8][96];
    __shared__ float2 part2[8][4][66];
    int tid = threadIdx.x;
    int ni = tid >> 5;
    int lane = tid & 31;
    int node = blockIdx.x * 8 + ni;

    for (int i = lane; i < 96; i += 32) wsm[ni][i] = wmat[(size_t)node * 96 + i];

    int beg = offs[node], end = offs[node + 1];
    float ninf = __int_as_float(0xff800000);
    float2 s  = make_float2(0.f, 0.f);
    float2 mx = make_float2(ninf, ninf);

    for (int j0 = beg; j0 < end; j0 += 32){
        int myv = (j0 + lane < end) ? csr[j0 + lane] : 0;
        int cnt = min(32, end - j0);
        int jj = 0;
        for (; jj + 4 <= cnt; jj += 4){
            int s0 = __shfl_sync(0xffffffffu, myv, jj);
            int s1 = __shfl_sync(0xffffffffu, myv, jj + 1);
            int s2 = __shfl_sync(0xffffffffu, myv, jj + 2);
            int s3 = __shfl_sync(0xffffffffu, myv, jj + 3);
            float2 v0 = __half22float2(basesH[(size_t)s0 * 32 + lane]);
            float2 v1 = __half22float2(basesH[(size_t)s1 * 32 + lane]);
            float2 v2 = __half22float2(basesH[(size_t)s2 * 32 + lane]);
            float2 v3 = __half22float2(basesH[(size_t)s3 * 32 + lane]);
            s.x += v0.x; s.y += v0.y;
            mx.x = fmaxf(mx.x, v0.x); mx.y = fmaxf(mx.y, v0.y);
            s.x += v1.x; s.y += v1.y;
            mx.x = fmaxf(mx.x, v1.x); mx.y = fmaxf(mx.y, v1.y);
            s.x += v2.x; s.y += v2.y;
            mx.x = fmaxf(mx.x, v2.x); mx.y = fmaxf(mx.y, v2.y);
            s.x += v3.x; s.y += v3.y;
            mx.x = fmaxf(mx.x, v3.x); mx.y = fmaxf(mx.y, v3.y);
        }
        for (; jj < cnt; jj++){
            int sv = __shfl_sync(0xffffffffu, myv, jj);
            float2 v = __half22float2(basesH[(size_t)sv * 32 + lane]);
            s.x += v.x; s.y += v.y;
            mx.x = fmaxf(mx.x, v.x); mx.y = fmaxf(mx.y, v.y);
        }
    }
    int deg = end - beg;
    float2 m;
    if (deg > 0){
        float inv = 1.f / (float)deg;
        m = make_float2(s.x * inv, s.y * inv);
    } else {
        m = make_float2(0.f, 0.f);
        mx = make_float2(0.f, 0.f);
    }
    __syncwarp();

    int b  = lane >> 3;
    int l8 = lane & 7;
    #pragma unroll
    for (int h = 0; h < 8; h++){
        float ws = wsm[ni][h * 12 + b];
        float wm = wsm[ni][h * 12 + 4 + b];
        float wx = wsm[ni][h * 12 + 8 + b];
        part2[ni][b][h * 8 + l8] = make_float2(ws * s.x + wm * m.x + wx * mx.x,
                                               ws * s.y + wm * m.y + wx * mx.y);
    }
    __syncwarp();

    const float2* convb2 = reinterpret_cast<const float2*>(convb);
    float2* gconv2 = reinterpret_cast<float2*>(gconv);
    #pragma unroll
    for (int c = lane; c < 64; c += 32){
        float2 p0 = part2[ni][0][c], p1 = part2[ni][1][c];
        float2 p2 = part2[ni][2][c], p3 = part2[ni][3][c];
        float2 cb = convb2[c];
        gconv2[(size_t)node * 64 + c] =
            make_float2(p0.x + p1.x + p2.x + p3.x + cb.x,
                        p0.y + p1.y + p2.y + p3.y + cb.y);
    }
}

// ---------------- GraphNorm: fused sum + sumsq (R9 exact) ----------------
__global__ void k_stats(const float* __restrict__ x, const int* __restrict__ gs,
                        float* __restrict__ gsum, float* __restrict__ gsq){
    int g = blockIdx.x, sp = blockIdx.y, S = gridDim.y;
    int beg = gs[g], end = gs[g + 1];
    int len = end - beg;
    int chunk = (len + S - 1) / S;
    int s0 = beg + sp * chunk;
    int s1 = min(s0 + chunk, end);
    if (s0 >= s1) return;
    int c = threadIdx.x;
    float a = 0.f, b = 0.f;
    for (int n = s0; n < s1; n++){
        float v = x[(size_t)n * 128 + c];
        a += v; b += v * v;
    }
    atomicAdd(&gsum[g * 128 + c], a);
    atomicAdd(&gsq[g * 128 + c], b);
}

// ---- norm: warp per node, float4 vectorized (R9 exact) ----
__global__ void __launch_bounds__(256) k_norm(
        float* __restrict__ h, const float* __restrict__ gc,
        const int* __restrict__ batch,
        const float* __restrict__ gsum, const float* __restrict__ gsq,
        const int* __restrict__ npg,
        const float* __restrict__ gnw, const float* __restrict__ gnb,
        const float* __restrict__ gnms){
    int tid = threadIdx.x;
    int node = blockIdx.x * 8 + (tid >> 5);
    int c = (tid & 31) * 4;
    if (node >= cfg::N) return;
    int g = __ldg(&batch[node]);
    float cnt = (float)max(npg[g], 1);
    float4 su = *reinterpret_cast<const float4*>(&gsum[g * 128 + c]);
    float4 sq = *reinterpret_cast<const float4*>(&gsq[g * 128 + c]);
    float4 ms = *reinterpret_cast<const float4*>(&gnms[c]);
    float4 wv = *reinterpret_cast<const float4*>(&gnw[c]);
    float4 bv = *reinterpret_cast<const float4*>(&gnb[c]);
    float4 gv = *reinterpret_cast<const float4*>(&gc[(size_t)node * 128 + c]);
    float4 hv = *reinterpret_cast<const float4*>(&h[(size_t)node * 128 + c]);
    float inv_cnt = 1.f / cnt;
    #pragma unroll
    for (int j = 0; j < 4; j++){
        float mu  = (&su.x)[j] * inv_cnt;
        float ex2 = (&sq.x)[j] * inv_cnt;
        float m   = (&ms.x)[j];
        float var = ex2 - mu * mu * m * (2.f - m);
        float inv = rsqrtf(fmaxf(var, 0.f) + cfg::EPS);
        float sub = (&gv.x)[j] - mu * m;
        float r = (&wv.x)[j] * sub * inv + (&bv.x)[j];
        (&hv.x)[j] += fmaxf(r, 0.f);
    }
    *reinterpret_cast<float4*>(&h[(size_t)node * 128 + c]) = hv;
}

__global__ void k_pool(const float* __restrict__ gsum, const int* __restrict__ npg,
                       float* __restrict__ y){
    int g = blockIdx.x, c = threadIdx.x;
    float cnt = (float)max(npg[g], 1);
    y[g * 128 + c] = gsum[g * 128 + c] / cnt;
}

// ---------------- launch ----------------
extern "C" void kernel_launch(void* const* d_in, const int* in_sizes, int n_in,
                              void* d_out, int out_size){
    using namespace cfg;
    const float* x      = (const float*)d_in[0];
    const int*   ei     = (const int*)  d_in[1];
    const int*   batch  = (const int*)  d_in[2];
    const int*   npg    = (const int*)  d_in[3];
    const float* lin_w  = (const float*)d_in[4];
    const float* lin_b  = (const float*)d_in[5];
    const float* basesw = (const float*)d_in[6];
    const float* combw  = (const float*)d_in[7];
    const float* combb  = (const float*)d_in[8];
    const float* convb  = (const float*)d_in[9];
    const float* gnw    = (const float*)d_in[10];
    const float* gnb    = (const float*)d_in[11];
    const float* gnms   = (const float*)d_in[12];

    float* h = (float*)d_out;
    float* y = h + (size_t)N * 128;

    void* sp = nullptr;
    cudaGetSymbolAddress(&sp, g_scratch);
    char* base = (char*)sp;
    int*   deg    = (int*)  (base + OFF_DEG);
    int*   cur    = (int*)  (base + OFF_CUR);
    int*   offs   = (int*)  (base + OFF_OFFS);
    int*   bsum   = (int*)  (base + OFF_BSUM);
    int*   csr    = (int*)  (base + OFF_CSR);
    int*   gst    = (int*)  (base + OFF_GST);
    float* basesF = (float*)(base + OFF_BASES);   // stored as half inside
    float* wF     = (float*)(base + OFF_W);
    float* gcF    = (float*)(base + OFF_GC);
    float* gsF    = (float*)(base + OFF_GS);
    float* gvF    = (float*)(base + OFF_GV);

    const int nb = (N + 1023) / 1024;
    constexpr int SMEM128 = 2 * 128 * 64 * 4;   // 65536
    constexpr int SMEM160 = 2 * 160 * 64 * 4;   // 81920

    cudaFuncSetAttribute(k_mma<128,128,0>, cudaFuncAttributeMaxDynamicSharedMemorySize, SMEM128);
    cudaFuncSetAttribute(k_mma<160,64,1>,  cudaFuncAttributeMaxDynamicSharedMemorySize, SMEM160);

    // lazily-created side stream + events (host resources; identical GPU work
    // each call, graph-capture fork/join via events)
    static cudaStream_t s1 = nullptr;
    static cudaEvent_t e0 = nullptr;
    static cudaEvent_t eR[LAYERS];               // norm(l) done (main)
    static cudaEvent_t eZ[LAYERS + 1];           // zero for layer l done (s1)
    if (!s1){
        cudaStreamCreateWithFlags(&s1, cudaStreamNonBlocking);
        cudaEventCreateWithFlags(&e0, cudaEventDisableTiming);
        for (int l = 0; l < LAYERS; l++)
            cudaEventCreateWithFlags(&eR[l], cudaEventDisableTiming);
        for (int l = 0; l <= LAYERS; l++)
            cudaEventCreateWithFlags(&eZ[l], cudaEventDisableTiming);
    }

    // ---- prologue: GEMMs on main stream, CSR build + first zero on s1 ----
    int zeroN = (int)(OFF_OFFS / 4);   // zeroes deg + cur (adjacent regions)
    k_mma<128,128,0><<<NT, 256, SMEM128>>>(x, N, lin_w, nullptr, lin_b, nullptr,
                                           h, nullptr);
    cudaEventRecord(e0, 0);
    cudaStreamWaitEvent(s1, e0, 0);
    k_zero<<<(zeroN + 255) / 256, 256, 0, s1>>>((unsigned int*)deg, zeroN);
    k_hist<<<(E + 255) / 256, 256, 0, s1>>>(ei, deg);
    k_mma<160,64,1><<<NT, 256, SMEM160>>>(               // 4th launch (profiled)
        h, N, basesw, combw, nullptr, combb, basesF, wF);
    k_scan1<<<nb, 1024, 0, s1>>>(deg, offs, bsum);
    k_scan2<<<1, 128, 0, s1>>>(bsum, nb);
    k_scan3<<<(N + 255) / 256, 256, 0, s1>>>(offs, bsum);
    k_fill<<<(E + 255) / 256, 256, 0, s1>>>(ei, offs, cur, csr);
    k_gstart<<<1, 32, 0, s1>>>(npg, gst);
    k_zero<<<(2 * G * 128 + 255) / 256, 256, 0, s1>>>((unsigned int*)gsF, 2 * G * 128);
    cudaEventRecord(eZ[0], s1);
    cudaStreamWaitEvent(0, eZ[0], 0);

    // ---- layers: per-layer gsF zero overlapped on s1 ----
    for (int l = 0; l < LAYERS; l++){
        if (l > 0)
            k_mma<160,64,1><<<NT, 256, SMEM160>>>(
                h, N, basesw + (size_t)l * 128 * 64, combw + (size_t)l * 128 * 96,
                nullptr, combb + (size_t)l * 96, basesF, wF);
        k_agg<<<N / 8, 256>>>((const __half2*)basesF, wF, offs, csr,
                              convb + (size_t)l * 128, gcF);
        if (l > 0) cudaStreamWaitEvent(0, eZ[l], 0);   // zero(gsF) done
        k_stats<<<dim3(G, 32), 128>>>(gcF, gst, gsF, gvF);
        k_norm<<<(N + 7) / 8, 256>>>(h, gcF, batch, gsF, gvF, npg,
                                     gnw + (size_t)l * 128, gnb + (size_t)l * 128,
                                     gnms + (size_t)l * 128);
        cudaEventRecord(eR[l], 0);
        cudaStreamWaitEvent(s1, eR[l], 0);             // gsF free after norm
        k_zero<<<(2 * G * 128 + 255) / 256, 256, 0, s1>>>((unsigned int*)gsF,
                                                          2 * G * 128);
        cudaEventRecord(eZ[l + 1], s1);
    }

    // ---- mean pool ----
    cudaStreamWaitEvent(0, eZ[LAYERS], 0);
    k_stats<<<dim3(G, 32), 128>>>(h, gst, gsF, gvF);
    k_pool<<<G, 128>>>(gsF, npg, y);
}